// round 4
// baseline (speedup 1.0000x reference)
#include <cuda_runtime.h>
#include <math_constants.h>

#define BQ 2048
#define NM 50000
#define DD 512
#define KT 16

// Scratch (static device globals — allocation-free per harness rules)
__device__ float  g_Qn[(size_t)BQ * DD];
__device__ float  g_Mn[(size_t)NM * DD];
__device__ float  g_sims[(size_t)BQ * NM];
__device__ double g_nq[BQ];
__device__ double g_nm[NM];

// ---------------------------------------------------------------------------
// Kernel 1: per-row L2 norm in fp64 (1 warp per row)
// ---------------------------------------------------------------------------
__global__ void norm_kernel(const float* __restrict__ X, int rows, int isquery) {
    int row  = blockIdx.x * 8 + (threadIdx.x >> 5);
    int lane = threadIdx.x & 31;
    if (row >= rows) return;
    const float4* p = (const float4*)(X + (size_t)row * DD);
    double s = 0.0;
#pragma unroll
    for (int j = 0; j < 4; j++) {
        float4 v = p[lane + 32 * j];
        s += (double)v.x * v.x + (double)v.y * v.y
           + (double)v.z * v.z + (double)v.w * v.w;
    }
#pragma unroll
    for (int o = 16; o > 0; o >>= 1) s += __shfl_xor_sync(0xffffffffu, s, o);
    if (lane == 0) {
        double n = sqrt(s);
        n = fmax(n, 1e-12);
        if (isquery) g_nq[row] = n; else g_nm[row] = n;
    }
}

// ---------------------------------------------------------------------------
// Kernel 2: normalize with fp64 division, single rounding to f32
// ---------------------------------------------------------------------------
__global__ void normalize_kernel(const float* __restrict__ X, int rows, int isquery) {
    int i = blockIdx.x * blockDim.x + threadIdx.x;   // float4 index
    int total = rows * (DD / 4);
    if (i >= total) return;
    int row = i >> 7;                                // / (DD/4)
    double n = isquery ? g_nq[row] : g_nm[row];
    float4 v = ((const float4*)X)[i];
    v.x = (float)((double)v.x / n);
    v.y = (float)((double)v.y / n);
    v.z = (float)((double)v.z / n);
    v.w = (float)((double)v.w / n);
    if (isquery) ((float4*)g_Qn)[i] = v; else ((float4*)g_Mn)[i] = v;
}

// ---------------------------------------------------------------------------
// Kernel 3: GEMM (NT): sims = Qn * Mn^T. fp32 FMA within K-chunks of 16,
// chunk partials folded into fp64 accumulators (near-exact sims).
// 128x128 tile, 512 threads, 4x8 micro-tile. Fused mask epilogue.
// ---------------------------------------------------------------------------
#define BM  128
#define BN  128
#define BKC 16
#define SPAD 132

__global__ __launch_bounds__(512, 2)
void sgemm_kernel(const int* __restrict__ qids, const int* __restrict__ mids) {
    __shared__ float As[BKC][SPAD];
    __shared__ float Bs[BKC][SPAD];

    int tid = threadIdx.x;
    int tx = tid & 15;       // 0..15 -> 8 cols
    int ty = tid >> 4;       // 0..31 -> 4 rows
    int q0 = blockIdx.y * BM;
    int n0 = blockIdx.x * BN;

    double accd[4][8];
#pragma unroll
    for (int i = 0; i < 4; i++)
#pragma unroll
        for (int j = 0; j < 8; j++) accd[i][j] = 0.0;

    for (int kc = 0; kc < DD; kc += BKC) {
        __syncthreads();
        {
            int r = tid >> 2;            // 0..127
            int c = (tid & 3) << 2;      // 0,4,8,12
            float4 va = *(const float4*)(g_Qn + (size_t)(q0 + r) * DD + kc + c);
            As[c + 0][r] = va.x; As[c + 1][r] = va.y;
            As[c + 2][r] = va.z; As[c + 3][r] = va.w;
            int nr = n0 + r;
            float4 vb = make_float4(0.f, 0.f, 0.f, 0.f);
            if (nr < NM) vb = *(const float4*)(g_Mn + (size_t)nr * DD + kc + c);
            Bs[c + 0][r] = vb.x; Bs[c + 1][r] = vb.y;
            Bs[c + 2][r] = vb.z; Bs[c + 3][r] = vb.w;
        }
        __syncthreads();

        float accf[4][8];
#pragma unroll
        for (int i = 0; i < 4; i++)
#pragma unroll
            for (int j = 0; j < 8; j++) accf[i][j] = 0.f;

#pragma unroll
        for (int k = 0; k < BKC; k++) {
            float4 ta = *(const float4*)&As[k][ty * 4];
            float4 t2 = *(const float4*)&Bs[k][tx * 8];
            float4 t3 = *(const float4*)&Bs[k][tx * 8 + 4];
            float a[4] = {ta.x, ta.y, ta.z, ta.w};
            float b[8] = {t2.x, t2.y, t2.z, t2.w, t3.x, t3.y, t3.z, t3.w};
#pragma unroll
            for (int i = 0; i < 4; i++)
#pragma unroll
                for (int j = 0; j < 8; j++)
                    accf[i][j] = fmaf(a[i], b[j], accf[i][j]);
        }
#pragma unroll
        for (int i = 0; i < 4; i++)
#pragma unroll
            for (int j = 0; j < 8; j++) accd[i][j] += (double)accf[i][j];
    }

    // Epilogue: self-id mask + threshold, write sims (-inf for invalid).
    int qid[4];
#pragma unroll
    for (int i = 0; i < 4; i++) qid[i] = qids[q0 + ty * 4 + i];
    int mid[8];
#pragma unroll
    for (int j = 0; j < 8; j++) {
        int n = n0 + tx * 8 + j;
        mid[j] = (n < NM) ? mids[n] : -1;
    }
#pragma unroll
    for (int i = 0; i < 4; i++) {
        size_t rb = (size_t)(q0 + ty * 4 + i) * NM;
#pragma unroll
        for (int jg = 0; jg < 2; jg++) {
            float4 o;
            float* op = &o.x;
#pragma unroll
            for (int j = 0; j < 4; j++) {
                int jj = jg * 4 + j;
                float s = (float)accd[i][jj];
                if (qid[i] == mid[jj] || s < 0.f) s = -CUDART_INF_F;
                op[j] = s;
            }
            int nc = n0 + tx * 8 + jg * 4;
            if (nc + 3 < NM) {
                *(float4*)(g_sims + rb + nc) = o;
            } else {
#pragma unroll
                for (int j = 0; j < 4; j++)
                    if (nc + j < NM) g_sims[rb + nc + j] = op[j];
            }
        }
    }
}

// ---------------------------------------------------------------------------
// Kernel 4: per-row top-16 + gather + output writes. 1 CTA per query row.
// Tie-break: equal values -> lower memory index first (lax.top_k stability).
// ---------------------------------------------------------------------------
__global__ __launch_bounds__(256)
void topk_kernel(const float* __restrict__ Mraw, const int* __restrict__ mids,
                 float* __restrict__ out) {
    int b = blockIdx.x;
    int tid = threadIdx.x;
    const float* row = g_sims + (size_t)b * NM;

    // thread-local sorted-ascending top-16 (v[0] = current min)
    float v[KT];
    int   id[KT];
#pragma unroll
    for (int s = 0; s < KT; s++) { v[s] = -CUDART_INF_F; id[s] = 0x7fffffff; }

    for (int i = tid * 4; i < NM; i += 1024) {
        float4 x = *(const float4*)(row + i);
        float xs[4] = {x.x, x.y, x.z, x.w};
#pragma unroll
        for (int j = 0; j < 4; j++) {
            float nv = xs[j];
            if (nv > v[0]) {
                v[0] = nv; id[0] = i + j;
#pragma unroll
                for (int s = 0; s < KT - 1; s++) {
                    if (v[s] > v[s + 1]) {
                        float tv = v[s]; v[s] = v[s + 1]; v[s + 1] = tv;
                        int ti = id[s]; id[s] = id[s + 1]; id[s + 1] = ti;
                    }
                }
            }
        }
    }

    __shared__ float sval[4096];
    __shared__ int   sidx[4096];
    __shared__ float rv[256];
    __shared__ int   ri[256];
    __shared__ int   rp[256];
    __shared__ float wv[KT];
    __shared__ int   wi[KT];

#pragma unroll
    for (int s = 0; s < KT; s++) {
        sval[tid * KT + s] = v[s];
        sidx[tid * KT + s] = id[s];
    }
    __syncthreads();

    // 16 rounds of block-wide argmax (descending, lower-index tie-break)
    for (int r = 0; r < KT; r++) {
        float bm = -CUDART_INF_F; int bi = 0x7fffffff; int bp = 0;
#pragma unroll
        for (int t = 0; t < 16; t++) {
            int p = tid + t * 256;
            float x = sval[p];
            int   xi = sidx[p];
            if (x > bm || (x == bm && xi < bi)) { bm = x; bi = xi; bp = p; }
        }
        rv[tid] = bm; ri[tid] = bi; rp[tid] = bp;
        __syncthreads();
        for (int st = 128; st > 0; st >>= 1) {
            if (tid < st) {
                float xo = rv[tid + st];
                if (xo > rv[tid] || (xo == rv[tid] && ri[tid + st] < ri[tid])) {
                    rv[tid] = xo; ri[tid] = ri[tid + st]; rp[tid] = rp[tid + st];
                }
            }
            __syncthreads();
        }
        if (tid == 0) {
            wv[r] = rv[0];
            wi[r] = ri[0];
            sval[rp[0]] = -CUDART_INF_F;
            sidx[rp[0]] = 0x7fffffff;
        }
        __syncthreads();
    }

    // Output layout (float32 concat, return order):
    //   retrieved [BQ,KT,DD] | top_sims [BQ,KT] | mask [BQ,KT] | ids [BQ,KT]
    const size_t OFF_SIMS = (size_t)BQ * KT * DD;
    const size_t OFF_MASK = OFF_SIMS + (size_t)BQ * KT;
    const size_t OFF_IDS  = OFF_MASK + (size_t)BQ * KT;

    if (tid < KT) {
        float val = wv[tid];
        bool valid = (val > -CUDART_INF_F);
        out[OFF_SIMS + (size_t)b * KT + tid] = val;
        out[OFF_MASK + (size_t)b * KT + tid] = valid ? 1.0f : 0.0f;
        out[OFF_IDS  + (size_t)b * KT + tid] = (float)mids[wi[tid]];
    }
    __syncthreads();

    // Gather raw memory vectors for the 16 winners (float4-vectorized)
    for (int e = tid; e < KT * (DD / 4); e += 256) {
        int kk = e >> 7;        // / (DD/4)
        int c4 = e & 127;
        int src = wi[kk];
        ((float4*)out)[((size_t)b * KT + kk) * (DD / 4) + c4] =
            ((const float4*)Mraw)[(size_t)src * (DD / 4) + c4];
    }
}

// ---------------------------------------------------------------------------
extern "C" void kernel_launch(void* const* d_in, const int* in_sizes, int n_in,
                              void* d_out, int out_size) {
    const float* Q    = (const float*)d_in[0];   // [2048, 512] f32
    const int*   qids = (const int*)  d_in[1];   // [2048] i32
    const float* M    = (const float*)d_in[2];   // [50000, 512] f32
    const int*   mids = (const int*)  d_in[3];   // [50000] i32
    float* out = (float*)d_out;

    norm_kernel<<<(NM + 7) / 8, 256>>>(M, NM, 0);
    norm_kernel<<<(BQ + 7) / 8, 256>>>(Q, BQ, 1);

    normalize_kernel<<<(NM * (DD / 4) + 255) / 256, 256>>>(M, NM, 0);
    normalize_kernel<<<(BQ * (DD / 4) + 255) / 256, 256>>>(Q, BQ, 1);

    dim3 grid((NM + BN - 1) / BN, BQ / BM);   // (391, 16)
    sgemm_kernel<<<grid, 512>>>(qids, mids);

    topk_kernel<<<BQ, 256>>>(M, mids, out);
}

// round 7
// speedup vs baseline: 2.3719x; 2.3719x over previous
#include <cuda_runtime.h>
#include <math_constants.h>

#define BQ 2048
#define NM 50000
#define DD 512
#define KT 16

// Scratch (static device globals — allocation-free per harness rules)
__device__ float  g_Qn[(size_t)BQ * DD];
__device__ float  g_Mn[(size_t)NM * DD];
__device__ float  g_sims[(size_t)BQ * NM];
__device__ double g_nq[BQ];
__device__ double g_nm[NM];

// ---------------------------------------------------------------------------
// Kernel 1: per-row L2 norm in fp64 (1 warp per row)  [identical to R3]
// ---------------------------------------------------------------------------
__global__ void norm_kernel(const float* __restrict__ X, int rows, int isquery) {
    int row  = blockIdx.x * 8 + (threadIdx.x >> 5);
    int lane = threadIdx.x & 31;
    if (row >= rows) return;
    const float4* p = (const float4*)(X + (size_t)row * DD);
    double s = 0.0;
#pragma unroll
    for (int j = 0; j < 4; j++) {
        float4 v = p[lane + 32 * j];
        s += (double)v.x * v.x + (double)v.y * v.y
           + (double)v.z * v.z + (double)v.w * v.w;
    }
#pragma unroll
    for (int o = 16; o > 0; o >>= 1) s += __shfl_xor_sync(0xffffffffu, s, o);
    if (lane == 0) {
        double n = sqrt(s);
        n = fmax(n, 1e-12);
        if (isquery) g_nq[row] = n; else g_nm[row] = n;
    }
}

// ---------------------------------------------------------------------------
// Kernel 2: normalize with fp64 division, single rounding  [identical to R3]
// ---------------------------------------------------------------------------
__global__ void normalize_kernel(const float* __restrict__ X, int rows, int isquery) {
    int i = blockIdx.x * blockDim.x + threadIdx.x;   // float4 index
    int total = rows * (DD / 4);
    if (i >= total) return;
    int row = i >> 7;                                // / (DD/4)
    double n = isquery ? g_nq[row] : g_nm[row];
    float4 v = ((const float4*)X)[i];
    v.x = (float)((double)v.x / n);
    v.y = (float)((double)v.y / n);
    v.z = (float)((double)v.z / n);
    v.w = (float)((double)v.w / n);
    if (isquery) ((float4*)g_Qn)[i] = v; else ((float4*)g_Mn)[i] = v;
}

// ---------------------------------------------------------------------------
// Kernel 3: GEMM (NT): sims = Qn * Mn^T.
// Numerics = R3 exactly: fp32 FMA within K-chunks of 16 (same per-accumulator
// op order), chunk partials folded with Kahan compensated fp32 summation
// (final s - c), exact to ~1 ulp — replaces R3's fp64 fold (fp64-pipe-bound).
// 128x128 tile, 256 threads, 8x8 micro-tile in two 4x8 halves, reg prefetch.
// ---------------------------------------------------------------------------
#define BM  128
#define BN  128
#define BK  16
#define SPAD 132

__global__ __launch_bounds__(256, 1)
void sgemm_kernel(const int* __restrict__ qids, const int* __restrict__ mids) {
    __shared__ float As[BK][SPAD];   // transposed: As[k][row]
    __shared__ float Bs[BK][SPAD];

    int tid = threadIdx.x;
    int tx = tid & 15;       // 0..15 -> 8 cols each
    int ty = tid >> 4;       // 0..15 -> 8 rows each
    int q0 = blockIdx.y * BM;
    int n0 = blockIdx.x * BN;

    // per-tile loads: 512 float4 / 256 threads = 2 each (f4 idx tid, tid+256)
    int lr0 = tid >> 2;             // row 0..63
    int lr1 = lr0 + 64;             // row 64..127
    int lk  = (tid & 3) << 2;       // k offset 0,4,8,12

    float s[8][8], c[8][8];
#pragma unroll
    for (int i = 0; i < 8; i++)
#pragma unroll
        for (int j = 0; j < 8; j++) { s[i][j] = 0.f; c[i][j] = 0.f; }

    // prefetch tile 0
    float4 pA0, pA1, pB0, pB1;
    {
        pA0 = *(const float4*)(g_Qn + (size_t)(q0 + lr0) * DD + lk);
        pA1 = *(const float4*)(g_Qn + (size_t)(q0 + lr1) * DD + lk);
        int nr0 = n0 + lr0, nr1 = n0 + lr1;
        pB0 = make_float4(0.f, 0.f, 0.f, 0.f);
        pB1 = make_float4(0.f, 0.f, 0.f, 0.f);
        if (nr0 < NM) pB0 = *(const float4*)(g_Mn + (size_t)nr0 * DD + lk);
        if (nr1 < NM) pB1 = *(const float4*)(g_Mn + (size_t)nr1 * DD + lk);
    }

    const int NIT = DD / BK;   // 32
    for (int it = 0; it < NIT; it++) {
        __syncthreads();
        As[lk + 0][lr0] = pA0.x; As[lk + 1][lr0] = pA0.y;
        As[lk + 2][lr0] = pA0.z; As[lk + 3][lr0] = pA0.w;
        As[lk + 0][lr1] = pA1.x; As[lk + 1][lr1] = pA1.y;
        As[lk + 2][lr1] = pA1.z; As[lk + 3][lr1] = pA1.w;
        Bs[lk + 0][lr0] = pB0.x; Bs[lk + 1][lr0] = pB0.y;
        Bs[lk + 2][lr0] = pB0.z; Bs[lk + 3][lr0] = pB0.w;
        Bs[lk + 0][lr1] = pB1.x; Bs[lk + 1][lr1] = pB1.y;
        Bs[lk + 2][lr1] = pB1.z; Bs[lk + 3][lr1] = pB1.w;
        __syncthreads();

        if (it + 1 < NIT) {
            int kc = (it + 1) * BK;
            pA0 = *(const float4*)(g_Qn + (size_t)(q0 + lr0) * DD + kc + lk);
            pA1 = *(const float4*)(g_Qn + (size_t)(q0 + lr1) * DD + kc + lk);
            int nr0 = n0 + lr0, nr1 = n0 + lr1;
            if (nr0 < NM) pB0 = *(const float4*)(g_Mn + (size_t)nr0 * DD + kc + lk);
            if (nr1 < NM) pB1 = *(const float4*)(g_Mn + (size_t)nr1 * DD + kc + lk);
        }

        // compute in two 4x8 halves (keeps accf at 32 regs); per-accumulator
        // FMA chain order over k is identical to R3.
#pragma unroll
        for (int h = 0; h < 2; h++) {
            float accf[4][8];
#pragma unroll
            for (int i = 0; i < 4; i++)
#pragma unroll
                for (int j = 0; j < 8; j++) accf[i][j] = 0.f;

#pragma unroll
            for (int k = 0; k < BK; k++) {
                float4 a  = *(const float4*)&As[k][ty * 8 + h * 4];
                float4 b0 = *(const float4*)&Bs[k][tx * 8];
                float4 b1 = *(const float4*)&Bs[k][tx * 8 + 4];
                float av[4] = {a.x, a.y, a.z, a.w};
                float bv[8] = {b0.x, b0.y, b0.z, b0.w, b1.x, b1.y, b1.z, b1.w};
#pragma unroll
                for (int i = 0; i < 4; i++)
#pragma unroll
                    for (int j = 0; j < 8; j++)
                        accf[i][j] = fmaf(av[i], bv[j], accf[i][j]);
            }
            // Kahan fold of this chunk partial
#pragma unroll
            for (int i = 0; i < 4; i++) {
                int ii = h * 4 + i;
#pragma unroll
                for (int j = 0; j < 8; j++) {
                    float y = accf[i][j] - c[ii][j];
                    float t = s[ii][j] + y;
                    c[ii][j] = (t - s[ii][j]) - y;
                    s[ii][j] = t;
                }
            }
        }
    }

    // Epilogue: self-id mask + threshold, write sims (-inf for invalid).
    int qid[8];
#pragma unroll
    for (int i = 0; i < 8; i++) qid[i] = qids[q0 + ty * 8 + i];
    int mid[8];
#pragma unroll
    for (int j = 0; j < 8; j++) {
        int n = n0 + tx * 8 + j;
        mid[j] = (n < NM) ? mids[n] : -1;
    }
#pragma unroll
    for (int i = 0; i < 8; i++) {
        size_t rb = (size_t)(q0 + ty * 8 + i) * NM;
#pragma unroll
        for (int jg = 0; jg < 2; jg++) {
            float4 o;
            float* op = &o.x;
#pragma unroll
            for (int j = 0; j < 4; j++) {
                int jj = jg * 4 + j;
                float v = s[i][jj] - c[i][jj];   // Kahan corrected sum
                if (qid[i] == mid[jj] || v < 0.f) v = -CUDART_INF_F;
                op[j] = v;
            }
            int nc = n0 + tx * 8 + jg * 4;
            if (nc + 3 < NM) {
                *(float4*)(g_sims + rb + nc) = o;
            } else {
#pragma unroll
                for (int j = 0; j < 4; j++)
                    if (nc + j < NM) g_sims[rb + nc + j] = op[j];
            }
        }
    }
}

// ---------------------------------------------------------------------------
// Kernel 4: per-row top-16 + gather + output writes. 1 CTA per query row.
// Tie-break: equal values -> lower memory index first (lax.top_k stability).
// [identical to R3]
// ---------------------------------------------------------------------------
__global__ __launch_bounds__(256)
void topk_kernel(const float* __restrict__ Mraw, const int* __restrict__ mids,
                 float* __restrict__ out) {
    int b = blockIdx.x;
    int tid = threadIdx.x;
    const float* row = g_sims + (size_t)b * NM;

    float v[KT];
    int   id[KT];
#pragma unroll
    for (int s = 0; s < KT; s++) { v[s] = -CUDART_INF_F; id[s] = 0x7fffffff; }

    for (int i = tid * 4; i < NM; i += 1024) {
        float4 x = *(const float4*)(row + i);
        float xs[4] = {x.x, x.y, x.z, x.w};
#pragma unroll
        for (int j = 0; j < 4; j++) {
            float nv = xs[j];
            if (nv > v[0]) {
                v[0] = nv; id[0] = i + j;
#pragma unroll
                for (int s = 0; s < KT - 1; s++) {
                    if (v[s] > v[s + 1]) {
                        float tv = v[s]; v[s] = v[s + 1]; v[s + 1] = tv;
                        int ti = id[s]; id[s] = id[s + 1]; id[s + 1] = ti;
                    }
                }
            }
        }
    }

    __shared__ float sval[4096];
    __shared__ int   sidx[4096];
    __shared__ float rv[256];
    __shared__ int   ri[256];
    __shared__ int   rp[256];
    __shared__ float wv[KT];
    __shared__ int   wi[KT];

#pragma unroll
    for (int s = 0; s < KT; s++) {
        sval[tid * KT + s] = v[s];
        sidx[tid * KT + s] = id[s];
    }
    __syncthreads();

    for (int r = 0; r < KT; r++) {
        float bm = -CUDART_INF_F; int bi = 0x7fffffff; int bp = 0;
#pragma unroll
        for (int t = 0; t < 16; t++) {
            int p = tid + t * 256;
            float x = sval[p];
            int   xi = sidx[p];
            if (x > bm || (x == bm && xi < bi)) { bm = x; bi = xi; bp = p; }
        }
        rv[tid] = bm; ri[tid] = bi; rp[tid] = bp;
        __syncthreads();
        for (int st = 128; st > 0; st >>= 1) {
            if (tid < st) {
                float xo = rv[tid + st];
                if (xo > rv[tid] || (xo == rv[tid] && ri[tid + st] < ri[tid])) {
                    rv[tid] = xo; ri[tid] = ri[tid + st]; rp[tid] = rp[tid + st];
                }
            }
            __syncthreads();
        }
        if (tid == 0) {
            wv[r] = rv[0];
            wi[r] = ri[0];
            sval[rp[0]] = -CUDART_INF_F;
            sidx[rp[0]] = 0x7fffffff;
        }
        __syncthreads();
    }

    const size_t OFF_SIMS = (size_t)BQ * KT * DD;
    const size_t OFF_MASK = OFF_SIMS + (size_t)BQ * KT;
    const size_t OFF_IDS  = OFF_MASK + (size_t)BQ * KT;

    if (tid < KT) {
        float val = wv[tid];
        bool valid = (val > -CUDART_INF_F);
        out[OFF_SIMS + (size_t)b * KT + tid] = val;
        out[OFF_MASK + (size_t)b * KT + tid] = valid ? 1.0f : 0.0f;
        out[OFF_IDS  + (size_t)b * KT + tid] = (float)mids[wi[tid]];
    }
    __syncthreads();

    for (int e = tid; e < KT * (DD / 4); e += 256) {
        int kk = e >> 7;
        int c4 = e & 127;
        int src = wi[kk];
        ((float4*)out)[((size_t)b * KT + kk) * (DD / 4) + c4] =
            ((const float4*)Mraw)[(size_t)src * (DD / 4) + c4];
    }
}

// ---------------------------------------------------------------------------
extern "C" void kernel_launch(void* const* d_in, const int* in_sizes, int n_in,
                              void* d_out, int out_size) {
    const float* Q    = (const float*)d_in[0];   // [2048, 512] f32
    const int*   qids = (const int*)  d_in[1];   // [2048] i32
    const float* M    = (const float*)d_in[2];   // [50000, 512] f32
    const int*   mids = (const int*)  d_in[3];   // [50000] i32
    float* out = (float*)d_out;

    norm_kernel<<<(NM + 7) / 8, 256>>>(M, NM, 0);
    norm_kernel<<<(BQ + 7) / 8, 256>>>(Q, BQ, 1);

    normalize_kernel<<<(NM * (DD / 4) + 255) / 256, 256>>>(M, NM, 0);
    normalize_kernel<<<(BQ * (DD / 4) + 255) / 256, 256>>>(Q, BQ, 1);

    dim3 grid((NM + BN - 1) / BN, BQ / BM);   // (391, 16)
    sgemm_kernel<<<grid, 256>>>(qids, mids);

    topk_kernel<<<BQ, 256>>>(M, mids, out);
}